// round 2
// baseline (speedup 1.0000x reference)
#include <cuda_runtime.h>
#include <math.h>

#define N_NODES 100000
#define N_EDGES 1600000
#define F_IN 128
#define D_OUT 64

static __device__ __constant__ float c_eps = 1e-3f;

// ---------------- scratch (static device arrays; no allocations) -------------
__device__ float g_colsum[F_IN];
__device__ float g_colsq[F_IN];
__device__ float g_mean[F_IN];
__device__ float g_rstd[F_IN];
__device__ float g_a1[N_NODES];
__device__ float g_a2[N_NODES];
__device__ float g_mapped[(size_t)N_NODES * D_OUT];
__device__ int   g_deg[N_NODES];
__device__ int   g_cur[N_NODES];
__device__ int   g_rowptr[N_NODES + 1];
__device__ int   g_bsum[128];
__device__ int   g_bscan[128];
__device__ int   g_cdst[N_EDGES];
__device__ float g_cval[N_EDGES];

// ---------------- kernel: zero counters --------------------------------------
__global__ void k_zero() {
    int i = blockIdx.x * blockDim.x + threadIdx.x;
    int stride = gridDim.x * blockDim.x;
    for (; i < N_NODES; i += stride) {
        g_deg[i] = 0;
        if (i < F_IN) { g_colsum[i] = 0.f; g_colsq[i] = 0.f; }
    }
}

// ---------------- kernel: per-feature sum / sumsq -----------------------------
__global__ void k_colstats(const float* __restrict__ x) {
    int f = threadIdx.x;  // 128 threads
    float s = 0.f, sq = 0.f;
    for (int row = blockIdx.x; row < N_NODES; row += gridDim.x) {
        float v = x[(size_t)row * F_IN + f];
        s += v; sq += v * v;
    }
    atomicAdd(&g_colsum[f], s);
    atomicAdd(&g_colsq[f], sq);
}

__global__ void k_finalize_stats() {
    int f = threadIdx.x;  // 128 threads, 1 block
    float mean = g_colsum[f] / (float)N_NODES;
    float var  = g_colsq[f] / (float)N_NODES - mean * mean;
    g_mean[f] = mean;
    g_rstd[f] = rsqrtf(var + c_eps);
}

// ---------------- kernel: degree histogram -----------------------------------
__global__ void k_hist(const int* __restrict__ src) {
    int i = blockIdx.x * blockDim.x + threadIdx.x;
    if (i < N_EDGES) atomicAdd(&g_deg[src[i]], 1);
}

// ---------------- scan (3 kernels): rowptr[i+1] = incl_scan(deg)[i] ----------
__global__ void k_scan1() {
    __shared__ int sh[1024];
    int tid = threadIdx.x;
    int i = blockIdx.x * 1024 + tid;
    int v = (i < N_NODES) ? g_deg[i] : 0;
    sh[tid] = v;
    __syncthreads();
    for (int off = 1; off < 1024; off <<= 1) {
        int t = (tid >= off) ? sh[tid - off] : 0;
        __syncthreads();
        sh[tid] += t;
        __syncthreads();
    }
    if (i < N_NODES) g_rowptr[i + 1] = sh[tid];
    if (tid == 1023) g_bsum[blockIdx.x] = sh[1023];
}

__global__ void k_scan2(int nb) {
    if (threadIdx.x == 0) {
        int run = 0;
        for (int j = 0; j < nb; ++j) { run += g_bsum[j]; g_bscan[j] = run; }
    }
}

__global__ void k_scan3() {
    int tid = threadIdx.x;
    int i = blockIdx.x * 1024 + tid;
    int add = (blockIdx.x > 0) ? g_bscan[blockIdx.x - 1] : 0;
    if (i < N_NODES) {
        g_rowptr[i + 1] += add;
        g_cur[i] = 0;
    }
    if (i == 0) g_rowptr[0] = 0;
}

// ---------------- kernel: scatter edges into CSR ------------------------------
__global__ void k_scatter(const int* __restrict__ src, const int* __restrict__ dst,
                          const float* __restrict__ vals) {
    int i = blockIdx.x * blockDim.x + threadIdx.x;
    if (i < N_EDGES) {
        int s = src[i];
        int p = g_rowptr[s] + atomicAdd(&g_cur[s], 1);
        g_cdst[p] = dst[i];
        g_cval[p] = vals[i];
    }
}

// ---------------- kernel: BN + 3 fused GEMMs (fp32) ---------------------------
// Persistent blocks; K1/K2/W resident in smem; 64-node tiles; 256 threads.
// For each node tile: mapped = xn@W, a1 = tanh(rowdot(xn@K1, xn)), a2 likewise.
#define BM 64
#define XPAD 132

__global__ void __launch_bounds__(256, 1) k_gemm(
    const float* __restrict__ x, const float* __restrict__ K1,
    const float* __restrict__ K2, const float* __restrict__ W)
{
    extern __shared__ float smem[];
    float* sK1 = smem;                      // 128*128
    float* sK2 = sK1 + F_IN * F_IN;         // 128*128
    float* sW  = sK2 + F_IN * F_IN;         // 128*64
    float* sX  = sW + F_IN * D_OUT;         // 64*XPAD

    int tid = threadIdx.x;
    // load weights once per block
    {
        const float4* K1v = (const float4*)K1;
        const float4* K2v = (const float4*)K2;
        float4* s1 = (float4*)sK1;
        float4* s2 = (float4*)sK2;
        for (int i = tid; i < F_IN * F_IN / 4; i += 256) { s1[i] = K1v[i]; s2[i] = K2v[i]; }
        const float4* Wv = (const float4*)W;
        float4* sw = (float4*)sW;
        for (int i = tid; i < F_IN * D_OUT / 4; i += 256) sw[i] = Wv[i];
    }
    int w = tid >> 5, l = tid & 31;
    float4 mn = ((const float4*)g_mean)[l];
    float4 rs = ((const float4*)g_rstd)[l];
    int ty = tid >> 4, tx = tid & 15;
    const int ntiles = (N_NODES + BM - 1) / BM;

    for (int tile = blockIdx.x; tile < ntiles; tile += gridDim.x) {
        int node0 = tile * BM;
        __syncthreads();  // protect sX vs previous tile readers
        // load + normalize x tile -> sX row-major [64][XPAD]
        #pragma unroll
        for (int rr = 0; rr < 8; ++rr) {
            int r = w * 8 + rr;
            int g = node0 + r;
            float4 xv = make_float4(0.f, 0.f, 0.f, 0.f);
            if (g < N_NODES) xv = ((const float4*)x)[(size_t)g * (F_IN / 4) + l];
            float4 xn;
            xn.x = (xv.x - mn.x) * rs.x;
            xn.y = (xv.y - mn.y) * rs.y;
            xn.z = (xv.z - mn.z) * rs.z;
            xn.w = (xv.w - mn.w) * rs.w;
            *(float4*)&sX[r * XPAD + 4 * l] = xn;
        }
        __syncthreads();

        int r0 = ty * 4;
        // ---- passes A/B: quadratic forms with K1 / K2 ----
        #pragma unroll
        for (int mm = 0; mm < 2; ++mm) {
            const float* sK = mm ? sK2 : sK1;
            int c0 = tx * 8;
            float acc[4][8];
            #pragma unroll
            for (int i = 0; i < 4; ++i)
                #pragma unroll
                for (int j = 0; j < 8; ++j) acc[i][j] = 0.f;
            #pragma unroll 4
            for (int k = 0; k < F_IN; ++k) {
                float a0 = sX[(r0 + 0) * XPAD + k];
                float a1v = sX[(r0 + 1) * XPAD + k];
                float a2v = sX[(r0 + 2) * XPAD + k];
                float a3 = sX[(r0 + 3) * XPAD + k];
                float4 b0 = *(const float4*)&sK[k * F_IN + c0];
                float4 b1 = *(const float4*)&sK[k * F_IN + c0 + 4];
                float bb[8] = {b0.x, b0.y, b0.z, b0.w, b1.x, b1.y, b1.z, b1.w};
                #pragma unroll
                for (int j = 0; j < 8; ++j) {
                    acc[0][j] += a0 * bb[j];
                    acc[1][j] += a1v * bb[j];
                    acc[2][j] += a2v * bb[j];
                    acc[3][j] += a3 * bb[j];
                }
            }
            // row-dot with xn over this thread's 8 cols
            float p[4];
            #pragma unroll
            for (int i = 0; i < 4; ++i) {
                float4 xa = *(const float4*)&sX[(r0 + i) * XPAD + c0];
                float4 xb = *(const float4*)&sX[(r0 + i) * XPAD + c0 + 4];
                p[i] = acc[i][0] * xa.x + acc[i][1] * xa.y + acc[i][2] * xa.z + acc[i][3] * xa.w
                     + acc[i][4] * xb.x + acc[i][5] * xb.y + acc[i][6] * xb.z + acc[i][7] * xb.w;
            }
            #pragma unroll
            for (int i = 0; i < 4; ++i) {
                #pragma unroll
                for (int off = 8; off > 0; off >>= 1)
                    p[i] += __shfl_down_sync(0xffffffffu, p[i], off, 16);
            }
            if (tx == 0) {
                float* dstp = mm ? g_a2 : g_a1;
                #pragma unroll
                for (int i = 0; i < 4; ++i) {
                    int g = node0 + r0 + i;
                    if (g < N_NODES) dstp[g] = tanhf(p[i]);
                }
            }
        }

        // ---- pass C: mapped = xn @ W ----
        {
            int c0 = tx * 4;
            float acc[4][4];
            #pragma unroll
            for (int i = 0; i < 4; ++i)
                #pragma unroll
                for (int j = 0; j < 4; ++j) acc[i][j] = 0.f;
            #pragma unroll 4
            for (int k = 0; k < F_IN; ++k) {
                float a0 = sX[(r0 + 0) * XPAD + k];
                float a1v = sX[(r0 + 1) * XPAD + k];
                float a2v = sX[(r0 + 2) * XPAD + k];
                float a3 = sX[(r0 + 3) * XPAD + k];
                float4 b = *(const float4*)&sW[k * D_OUT + c0];
                float bb[4] = {b.x, b.y, b.z, b.w};
                #pragma unroll
                for (int j = 0; j < 4; ++j) {
                    acc[0][j] += a0 * bb[j];
                    acc[1][j] += a1v * bb[j];
                    acc[2][j] += a2v * bb[j];
                    acc[3][j] += a3 * bb[j];
                }
            }
            #pragma unroll
            for (int i = 0; i < 4; ++i) {
                int g = node0 + r0 + i;
                if (g < N_NODES) {
                    float4 o = make_float4(acc[i][0], acc[i][1], acc[i][2], acc[i][3]);
                    *(float4*)&g_mapped[(size_t)g * D_OUT + c0] = o;
                }
            }
        }
    }
}

// ---------------- kernel: fused edge softmax + SpMM + tanh --------------------
// One warp per node. Pass 1: segment max. Pass 2: exp/sum + accumulate
// attn-weighted mapped[dst]; each lane owns 2 of the 64 output dims.
__global__ void k_spmm(float* __restrict__ out) {
    int node = blockIdx.x * 8 + (threadIdx.x >> 5);
    if (node >= N_NODES) return;
    int lane = threadIdx.x & 31;
    int s = g_rowptr[node];
    int e = g_rowptr[node + 1];
    float a1i = g_a1[node];

    float m = -1e30f;
    for (int j = s + lane; j < e; j += 32) {
        int d = g_cdst[j];
        float v = g_cval[j];
        float t = v * (a1i + g_a2[d]);
        t = t > 0.f ? t : 0.2f * t;
        m = fmaxf(m, t);
    }
    #pragma unroll
    for (int off = 16; off > 0; off >>= 1)
        m = fmaxf(m, __shfl_xor_sync(0xffffffffu, m, off));

    float2 acc = make_float2(0.f, 0.f);
    float den = 0.f;
    const float2* map2 = (const float2*)g_mapped;
    for (int j = s; j < e; ++j) {
        int d = g_cdst[j];
        float v = g_cval[j];
        float t = v * (a1i + g_a2[d]);
        t = t > 0.f ? t : 0.2f * t;
        float wgt = __expf(t - m);
        den += wgt;
        float2 md = map2[(size_t)d * 32 + lane];
        acc.x += wgt * md.x;
        acc.y += wgt * md.y;
    }
    float2 o;
    if (e > s) {
        float inv = 1.f / den;
        o.x = tanhf(acc.x * inv);
        o.y = tanhf(acc.y * inv);
    } else {
        o = make_float2(0.f, 0.f);
    }
    ((float2*)out)[(size_t)node * 32 + lane] = o;
}

// ---------------- launch -------------------------------------------------------
extern "C" void kernel_launch(void* const* d_in, const int* in_sizes, int n_in,
                              void* d_out, int out_size) {
    const float* x    = (const float*)d_in[0];
    const int*   src  = (const int*)d_in[1];
    const int*   dst  = (const int*)d_in[2];
    const float* vals = (const float*)d_in[3];
    const float* W    = (const float*)d_in[4];
    const float* K1   = (const float*)d_in[5];
    const float* K2   = (const float*)d_in[6];
    float* out = (float*)d_out;

    const int NB = (N_NODES + 1023) / 1024;   // 98
    const int EB = (N_EDGES + 255) / 256;     // 6250

    k_zero<<<512, 256>>>();
    k_colstats<<<1184, 128>>>(x);
    k_finalize_stats<<<1, 128>>>();

    k_hist<<<EB, 256>>>(src);
    k_scan1<<<NB, 1024>>>();
    k_scan2<<<1, 32>>>(NB);
    k_scan3<<<NB, 1024>>>();
    k_scatter<<<EB, 256>>>(src, dst, vals);

    size_t smem = (size_t)(F_IN * F_IN * 2 + F_IN * D_OUT + BM * XPAD) * sizeof(float);
    cudaFuncSetAttribute(k_gemm, cudaFuncAttributeMaxDynamicSharedMemorySize, (int)smem);
    k_gemm<<<152, 256, smem>>>(x, K1, K2, W);

    k_spmm<<<(N_NODES + 7) / 8, 256>>>(out);
}

// round 4
// speedup vs baseline: 1.7773x; 1.7773x over previous
#include <cuda_runtime.h>
#include <cuda_bf16.h>
#include <stdint.h>
#include <math.h>

#define N_NODES 100000
#define N_EDGES 1600000
#define F_IN 128
#define D_OUT 64
#define PADK 136   // bf16 elems per smem row (128 + 8 pad, conflict-free)

static __device__ __constant__ float c_eps = 1e-3f;

// ---------------- scratch ------------------------------------------------------
__device__ float g_colsum[F_IN];
__device__ float g_colsq[F_IN];
__device__ float g_mean[F_IN];
__device__ float g_rstd[F_IN];
__device__ float g_a1[N_NODES];
__device__ float g_a2[N_NODES];
__device__ float g_mapped[(size_t)N_NODES * D_OUT];
__device__ int   g_deg[N_NODES];
__device__ int   g_cur[N_NODES];
__device__ int   g_rowptr[N_NODES + 1];
__device__ int   g_bsum[128];
__device__ int   g_bscan[128];
__device__ int   g_cdst[N_EDGES];
__device__ float g_cval[N_EDGES];

// ---------------- small kernels -------------------------------------------------
__global__ void k_zero() {
    int i = blockIdx.x * blockDim.x + threadIdx.x;
    int stride = gridDim.x * blockDim.x;
    for (; i < N_NODES; i += stride) {
        g_deg[i] = 0;
        if (i < F_IN) { g_colsum[i] = 0.f; g_colsq[i] = 0.f; }
    }
}

__global__ void k_colstats(const float* __restrict__ x) {
    int f = threadIdx.x;
    float s = 0.f, sq = 0.f;
    for (int row = blockIdx.x; row < N_NODES; row += gridDim.x) {
        float v = x[(size_t)row * F_IN + f];
        s += v; sq += v * v;
    }
    atomicAdd(&g_colsum[f], s);
    atomicAdd(&g_colsq[f], sq);
}

__global__ void k_finalize_stats() {
    int f = threadIdx.x;
    float mean = g_colsum[f] / (float)N_NODES;
    float var  = g_colsq[f] / (float)N_NODES - mean * mean;
    g_mean[f] = mean;
    g_rstd[f] = rsqrtf(var + c_eps);
}

__global__ void k_hist(const int* __restrict__ src) {
    int i = blockIdx.x * blockDim.x + threadIdx.x;
    if (i < N_EDGES) atomicAdd(&g_deg[src[i]], 1);
}

__global__ void k_scan1() {
    __shared__ int sh[1024];
    int tid = threadIdx.x;
    int i = blockIdx.x * 1024 + tid;
    int v = (i < N_NODES) ? g_deg[i] : 0;
    sh[tid] = v;
    __syncthreads();
    for (int off = 1; off < 1024; off <<= 1) {
        int t = (tid >= off) ? sh[tid - off] : 0;
        __syncthreads();
        sh[tid] += t;
        __syncthreads();
    }
    if (i < N_NODES) g_rowptr[i + 1] = sh[tid];
    if (tid == 1023) g_bsum[blockIdx.x] = sh[1023];
}

__global__ void k_scan2(int nb) {
    if (threadIdx.x == 0) {
        int run = 0;
        for (int j = 0; j < nb; ++j) { run += g_bsum[j]; g_bscan[j] = run; }
    }
}

__global__ void k_scan3() {
    int tid = threadIdx.x;
    int i = blockIdx.x * 1024 + tid;
    int add = (blockIdx.x > 0) ? g_bscan[blockIdx.x - 1] : 0;
    if (i < N_NODES) {
        g_rowptr[i + 1] += add;
        g_cur[i] = 0;
    }
    if (i == 0) g_rowptr[0] = 0;
}

__global__ void k_scatter(const int* __restrict__ src, const int* __restrict__ dst,
                          const float* __restrict__ vals) {
    int i = blockIdx.x * blockDim.x + threadIdx.x;
    if (i < N_EDGES) {
        int s = src[i];
        int p = g_rowptr[s] + atomicAdd(&g_cur[s], 1);
        g_cdst[p] = dst[i];
        g_cval[p] = vals[i];
    }
}

// ---------------- tensor-core GEMM block ----------------------------------------
// BN + xn@[K1|K2|W] via mma.sync m16n8k16 bf16, 3-term hi/lo split (fp32-class).
// Weights transposed+split resident in smem. Quadratic-form rowdots computed
// straight from accumulator fragments. 256 threads, 64-row tiles, persistent.

__device__ __forceinline__ void bsplit(float v, __nv_bfloat16& h, __nv_bfloat16& l) {
    h = __float2bfloat16(v);
    l = __float2bfloat16(v - __bfloat162float(h));
}

#define MMA16816(D, A, B0, B1)                                               \
    asm volatile(                                                            \
        "mma.sync.aligned.m16n8k16.row.col.f32.bf16.bf16.f32 "              \
        "{%0,%1,%2,%3}, {%4,%5,%6,%7}, {%8,%9}, {%0,%1,%2,%3};"             \
        : "+f"(D[0]), "+f"(D[1]), "+f"(D[2]), "+f"(D[3])                     \
        : "r"(A[0]), "r"(A[1]), "r"(A[2]), "r"(A[3]), "r"(B0), "r"(B1))

__global__ void __launch_bounds__(256, 1) k_gemm(
    const float* __restrict__ x, const float* __restrict__ K1,
    const float* __restrict__ K2, const float* __restrict__ W)
{
    extern __shared__ __nv_bfloat16 smem[];
    __nv_bfloat16* sK1h = smem;                    // [128][PADK]
    __nv_bfloat16* sK1l = sK1h + F_IN * PADK;
    __nv_bfloat16* sK2h = sK1l + F_IN * PADK;
    __nv_bfloat16* sK2l = sK2h + F_IN * PADK;
    __nv_bfloat16* sWh  = sK2l + F_IN * PADK;      // [64][PADK]
    __nv_bfloat16* sWl  = sWh + D_OUT * PADK;
    __nv_bfloat16* sXh  = sWl + D_OUT * PADK;      // [64][PADK]
    __nv_bfloat16* sXl  = sXh + 64 * PADK;
    float* sD1 = (float*)(sXl + 64 * PADK);        // [64][2]
    float* sD2 = sD1 + 128;                        // [64][2]

    int tid = threadIdx.x;

    // ---- load + transpose + split weights (once per block) ----
    for (int i = tid; i < F_IN * F_IN; i += 256) {
        int k = i >> 7, n = i & 127;
        __nv_bfloat16 h, l;
        bsplit(K1[i], h, l); sK1h[n * PADK + k] = h; sK1l[n * PADK + k] = l;
        bsplit(K2[i], h, l); sK2h[n * PADK + k] = h; sK2l[n * PADK + k] = l;
    }
    for (int i = tid; i < F_IN * D_OUT; i += 256) {
        int k = i >> 6, n = i & 63;
        __nv_bfloat16 h, l;
        bsplit(W[i], h, l); sWh[n * PADK + k] = h; sWl[n * PADK + k] = l;
    }

    int w = tid >> 5, lane = tid & 31;
    int g = lane >> 2, tig = lane & 3;
    int wr = w >> 1, wc = w & 1;
    int r0 = wr * 16;

    float4 mn = ((const float4*)g_mean)[lane];
    float4 rs = ((const float4*)g_rstd)[lane];

    const int ntiles = (N_NODES + 63) / 64;
    for (int tile = blockIdx.x; tile < ntiles; tile += gridDim.x) {
        int node0 = tile * 64;
        __syncthreads();   // prior tile fully consumed (sX, sD)

        // ---- load + BN + split x tile: warp w rows w*8..+7, lane cols 4*lane ----
        #pragma unroll
        for (int rr = 0; rr < 8; ++rr) {
            int r = w * 8 + rr;
            int gn = node0 + r;
            float4 xv = make_float4(0.f, 0.f, 0.f, 0.f);
            if (gn < N_NODES) xv = ((const float4*)x)[(size_t)gn * (F_IN / 4) + lane];
            float xn[4];
            xn[0] = (xv.x - mn.x) * rs.x;
            xn[1] = (xv.y - mn.y) * rs.y;
            xn[2] = (xv.z - mn.z) * rs.z;
            xn[3] = (xv.w - mn.w) * rs.w;
            __nv_bfloat16 h[4], l[4];
            #pragma unroll
            for (int c = 0; c < 4; ++c) bsplit(xn[c], h[c], l[c]);
            int base = r * PADK + 4 * lane;
            *(__nv_bfloat162*)&sXh[base]     = __nv_bfloat162(h[0], h[1]);
            *(__nv_bfloat162*)&sXh[base + 2] = __nv_bfloat162(h[2], h[3]);
            *(__nv_bfloat162*)&sXl[base]     = __nv_bfloat162(l[0], l[1]);
            *(__nv_bfloat162*)&sXl[base + 2] = __nv_bfloat162(l[2], l[3]);
        }
        __syncthreads();

        // ---- MMA: rows r0..r0+15, cols (wc half) of [K1|K2|W] ----
        float aK1[8][4], aK2[8][4], aW[4][4];
        #pragma unroll
        for (int t = 0; t < 8; ++t)
            #pragma unroll
            for (int i = 0; i < 4; ++i) { aK1[t][i] = 0.f; aK2[t][i] = 0.f; }
        #pragma unroll
        for (int t = 0; t < 4; ++t)
            #pragma unroll
            for (int i = 0; i < 4; ++i) aW[t][i] = 0.f;

        #pragma unroll
        for (int ks = 0; ks < 8; ++ks) {
            int k0 = ks * 16;
            uint32_t ah[4], al[4];
            int ra = (r0 + g) * PADK + k0 + 2 * tig;
            int rb = (r0 + g + 8) * PADK + k0 + 2 * tig;
            ah[0] = *(const uint32_t*)&sXh[ra];
            ah[1] = *(const uint32_t*)&sXh[rb];
            ah[2] = *(const uint32_t*)&sXh[ra + 8];
            ah[3] = *(const uint32_t*)&sXh[rb + 8];
            al[0] = *(const uint32_t*)&sXl[ra];
            al[1] = *(const uint32_t*)&sXl[rb];
            al[2] = *(const uint32_t*)&sXl[ra + 8];
            al[3] = *(const uint32_t*)&sXl[rb + 8];

            #pragma unroll
            for (int t = 0; t < 8; ++t) {
                int nb = (wc * 64 + t * 8 + g) * PADK + k0 + 2 * tig;
                uint32_t bh0 = *(const uint32_t*)&sK1h[nb];
                uint32_t bh1 = *(const uint32_t*)&sK1h[nb + 8];
                uint32_t bl0 = *(const uint32_t*)&sK1l[nb];
                uint32_t bl1 = *(const uint32_t*)&sK1l[nb + 8];
                MMA16816(aK1[t], ah, bh0, bh1);
                MMA16816(aK1[t], ah, bl0, bl1);
                MMA16816(aK1[t], al, bh0, bh1);
            }
            #pragma unroll
            for (int t = 0; t < 8; ++t) {
                int nb = (wc * 64 + t * 8 + g) * PADK + k0 + 2 * tig;
                uint32_t bh0 = *(const uint32_t*)&sK2h[nb];
                uint32_t bh1 = *(const uint32_t*)&sK2h[nb + 8];
                uint32_t bl0 = *(const uint32_t*)&sK2l[nb];
                uint32_t bl1 = *(const uint32_t*)&sK2l[nb + 8];
                MMA16816(aK2[t], ah, bh0, bh1);
                MMA16816(aK2[t], ah, bl0, bl1);
                MMA16816(aK2[t], al, bh0, bh1);
            }
            #pragma unroll
            for (int t = 0; t < 4; ++t) {
                int nb = (wc * 32 + t * 8 + g) * PADK + k0 + 2 * tig;
                uint32_t bh0 = *(const uint32_t*)&sWh[nb];
                uint32_t bh1 = *(const uint32_t*)&sWh[nb + 8];
                uint32_t bl0 = *(const uint32_t*)&sWl[nb];
                uint32_t bl1 = *(const uint32_t*)&sWl[nb + 8];
                MMA16816(aW[t], ah, bh0, bh1);
                MMA16816(aW[t], ah, bl0, bl1);
                MMA16816(aW[t], al, bh0, bh1);
            }
        }

        // ---- quadratic-form rowdots from fragments ----
        {
            int rA = r0 + g, rB = r0 + g + 8;
            float p0 = 0.f, p1 = 0.f, q0 = 0.f, q1 = 0.f;
            #pragma unroll
            for (int t = 0; t < 8; ++t) {
                int c0 = wc * 64 + t * 8 + 2 * tig;
                float xA0 = __bfloat162float(sXh[rA * PADK + c0])     + __bfloat162float(sXl[rA * PADK + c0]);
                float xA1 = __bfloat162float(sXh[rA * PADK + c0 + 1]) + __bfloat162float(sXl[rA * PADK + c0 + 1]);
                float xB0 = __bfloat162float(sXh[rB * PADK + c0])     + __bfloat162float(sXl[rB * PADK + c0]);
                float xB1 = __bfloat162float(sXh[rB * PADK + c0 + 1]) + __bfloat162float(sXl[rB * PADK + c0 + 1]);
                p0 += aK1[t][0] * xA0 + aK1[t][1] * xA1;
                p1 += aK1[t][2] * xB0 + aK1[t][3] * xB1;
                q0 += aK2[t][0] * xA0 + aK2[t][1] * xA1;
                q1 += aK2[t][2] * xB0 + aK2[t][3] * xB1;
            }
            p0 += __shfl_xor_sync(0xffffffffu, p0, 1); p0 += __shfl_xor_sync(0xffffffffu, p0, 2);
            p1 += __shfl_xor_sync(0xffffffffu, p1, 1); p1 += __shfl_xor_sync(0xffffffffu, p1, 2);
            q0 += __shfl_xor_sync(0xffffffffu, q0, 1); q0 += __shfl_xor_sync(0xffffffffu, q0, 2);
            q1 += __shfl_xor_sync(0xffffffffu, q1, 1); q1 += __shfl_xor_sync(0xffffffffu, q1, 2);
            if (tig == 0) {
                sD1[rA * 2 + wc] = p0; sD1[rB * 2 + wc] = p1;
                sD2[rA * 2 + wc] = q0; sD2[rB * 2 + wc] = q1;
            }
        }

        // ---- store mapped = xn @ W ----
        #pragma unroll
        for (int t = 0; t < 4; ++t) {
            int c0 = wc * 32 + t * 8 + 2 * tig;
            int gA = node0 + r0 + g, gB = gA + 8;
            if (gA < N_NODES)
                *(float2*)&g_mapped[(size_t)gA * D_OUT + c0] = make_float2(aW[t][0], aW[t][1]);
            if (gB < N_NODES)
                *(float2*)&g_mapped[(size_t)gB * D_OUT + c0] = make_float2(aW[t][2], aW[t][3]);
        }

        __syncthreads();
        if (tid < 64) {
            int gn = node0 + tid;
            if (gn < N_NODES) {
                g_a1[gn] = tanhf(sD1[tid * 2] + sD1[tid * 2 + 1]);
                g_a2[gn] = tanhf(sD2[tid * 2] + sD2[tid * 2 + 1]);
            }
        }
    }
}

// ---------------- fused single-pass softmax + SpMM + tanh -----------------------
// No segment-max needed: |e| = |v*(tanh+tanh)| <= 2*max|v|, exp never overflows
// and softmax is shift-invariant, so result is identical to the reference.
__global__ void k_spmm(float* __restrict__ out) {
    int node = blockIdx.x * 8 + (threadIdx.x >> 5);
    if (node >= N_NODES) return;
    int lane = threadIdx.x & 31;
    int s = g_rowptr[node];
    int e = g_rowptr[node + 1];
    float a1i = g_a1[node];

    float2 acc = make_float2(0.f, 0.f);
    float den = 0.f;
    const float2* map2 = (const float2*)g_mapped;
    for (int j = s; j < e; ++j) {
        int d = g_cdst[j];
        float v = g_cval[j];
        float t = v * (a1i + g_a2[d]);
        t = t > 0.f ? t : 0.2f * t;
        float wgt = __expf(t);
        float2 md = map2[(size_t)d * 32 + lane];
        den += wgt;
        acc.x += wgt * md.x;
        acc.y += wgt * md.y;
    }
    float2 o;
    if (e > s) {
        float inv = 1.f / den;
        o.x = tanhf(acc.x * inv);
        o.y = tanhf(acc.y * inv);
    } else {
        o = make_float2(0.f, 0.f);
    }
    ((float2*)out)[(size_t)node * 32 + lane] = o;
}

// ---------------- launch ---------------------------------------------------------
extern "C" void kernel_launch(void* const* d_in, const int* in_sizes, int n_in,
                              void* d_out, int out_size) {
    const float* x    = (const float*)d_in[0];
    const int*   src  = (const int*)d_in[1];
    const int*   dst  = (const int*)d_in[2];
    const float* vals = (const float*)d_in[3];
    const float* W    = (const float*)d_in[4];
    const float* K1   = (const float*)d_in[5];
    const float* K2   = (const float*)d_in[6];
    float* out = (float*)d_out;

    const int NB = (N_NODES + 1023) / 1024;
    const int EB = (N_EDGES + 255) / 256;

    k_zero<<<512, 256>>>();
    k_colstats<<<1184, 128>>>(x);
    k_finalize_stats<<<1, 128>>>();

    k_hist<<<EB, 256>>>(src);
    k_scan1<<<NB, 1024>>>();
    k_scan2<<<1, 32>>>(NB);
    k_scan3<<<NB, 1024>>>();
    k_scatter<<<EB, 256>>>(src, dst, vals);

    size_t smem = (size_t)(4 * F_IN * PADK + 2 * D_OUT * PADK + 2 * 64 * PADK) * sizeof(__nv_bfloat16)
                + 256 * sizeof(float);
    cudaFuncSetAttribute(k_gemm, cudaFuncAttributeMaxDynamicSharedMemorySize, (int)smem);
    k_gemm<<<148, 256, smem>>>(x, K1, K2, W);

    k_spmm<<<(N_NODES + 7) / 8, 256>>>(out);
}

// round 5
// speedup vs baseline: 2.0393x; 1.1474x over previous
#include <cuda_runtime.h>
#include <cuda_bf16.h>
#include <stdint.h>
#include <math.h>

#define N_NODES 100000
#define N_EDGES 1600000
#define F_IN 128
#define D_OUT 64
#define PADK 136   // bf16 elems per smem row (128 + 8 pad, conflict-free)

static __device__ __constant__ float c_eps = 1e-3f;

// ---------------- scratch ------------------------------------------------------
__device__ float g_colsum[F_IN];
__device__ float g_colsq[F_IN];
__device__ float g_mean[F_IN];
__device__ float g_rstd[F_IN];
__device__ float g_a1[N_NODES];
__device__ float g_a2[N_NODES];
__device__ float g_mapped[(size_t)N_NODES * D_OUT];
__device__ int   g_deg[N_NODES];
__device__ int   g_cur[N_NODES];
__device__ int   g_rowptr[N_NODES + 1];
__device__ int   g_bsum[128];
__device__ int   g_bscan[128];
__device__ int   g_cdst[N_EDGES];
__device__ float g_cval[N_EDGES];

// ---------------- small kernels -------------------------------------------------
__global__ void k_zero() {
    int i = blockIdx.x * blockDim.x + threadIdx.x;
    int stride = gridDim.x * blockDim.x;
    for (; i < N_NODES; i += stride) {
        g_deg[i] = 0;
        if (i < F_IN) { g_colsum[i] = 0.f; g_colsq[i] = 0.f; }
    }
}

__global__ void k_colstats(const float* __restrict__ x) {
    int f = threadIdx.x & 127;        // 256 threads: 2 rows per block-iter
    int half = threadIdx.x >> 7;
    float s = 0.f, sq = 0.f;
    for (int row = blockIdx.x * 2 + half; row < N_NODES; row += gridDim.x * 2) {
        float v = x[(size_t)row * F_IN + f];
        s += v; sq += v * v;
    }
    atomicAdd(&g_colsum[f], s);
    atomicAdd(&g_colsq[f], sq);
}

__global__ void k_finalize_stats() {
    int f = threadIdx.x;
    float mean = g_colsum[f] / (float)N_NODES;
    float var  = g_colsq[f] / (float)N_NODES - mean * mean;
    g_mean[f] = mean;
    g_rstd[f] = rsqrtf(var + c_eps);
}

__global__ void k_hist(const int* __restrict__ src) {
    int i = blockIdx.x * blockDim.x + threadIdx.x;
    if (i < N_EDGES) atomicAdd(&g_deg[src[i]], 1);
}

__global__ void k_scan1() {
    __shared__ int sh[1024];
    int tid = threadIdx.x;
    int i = blockIdx.x * 1024 + tid;
    int v = (i < N_NODES) ? g_deg[i] : 0;
    sh[tid] = v;
    __syncthreads();
    for (int off = 1; off < 1024; off <<= 1) {
        int t = (tid >= off) ? sh[tid - off] : 0;
        __syncthreads();
        sh[tid] += t;
        __syncthreads();
    }
    if (i < N_NODES) g_rowptr[i + 1] = sh[tid];
    if (tid == 1023) g_bsum[blockIdx.x] = sh[1023];
}

__global__ void k_scan2(int nb) {   // parallel scan of <=128 block sums
    __shared__ int sh[128];
    int t = threadIdx.x;
    int v = (t < nb) ? g_bsum[t] : 0;
    sh[t] = v;
    __syncthreads();
    for (int off = 1; off < 128; off <<= 1) {
        int u = (t >= off) ? sh[t - off] : 0;
        __syncthreads();
        sh[t] += u;
        __syncthreads();
    }
    if (t < nb) g_bscan[t] = sh[t];
}

__global__ void k_scan3() {
    int tid = threadIdx.x;
    int i = blockIdx.x * 1024 + tid;
    int add = (blockIdx.x > 0) ? g_bscan[blockIdx.x - 1] : 0;
    if (i < N_NODES) {
        g_rowptr[i + 1] += add;
        g_cur[i] = 0;
    }
    if (i == 0) g_rowptr[0] = 0;
}

__global__ void k_scatter(const int* __restrict__ src, const int* __restrict__ dst,
                          const float* __restrict__ vals) {
    int i = blockIdx.x * blockDim.x + threadIdx.x;
    if (i < N_EDGES) {
        int s = src[i];
        int p = g_rowptr[s] + atomicAdd(&g_cur[s], 1);
        g_cdst[p] = dst[i];
        g_cval[p] = vals[i];
    }
}

// ---------------- tensor-core GEMM block ----------------------------------------
// BN + xn@[K1|K2|W] via mma.sync m16n8k16 bf16, 3-term hi/lo split (fp32-class).
// Weights transposed+split resident in smem. Quadratic-form rowdots computed
// straight from accumulator fragments. 256 threads, 64-row tiles, persistent.

__device__ __forceinline__ void bsplit(float v, __nv_bfloat16& h, __nv_bfloat16& l) {
    h = __float2bfloat16(v);
    l = __float2bfloat16(v - __bfloat162float(h));
}

#define MMA16816(D, A, B0, B1)                                               \
    asm volatile(                                                            \
        "mma.sync.aligned.m16n8k16.row.col.f32.bf16.bf16.f32 "              \
        "{%0,%1,%2,%3}, {%4,%5,%6,%7}, {%8,%9}, {%0,%1,%2,%3};"             \
        : "+f"(D[0]), "+f"(D[1]), "+f"(D[2]), "+f"(D[3])                     \
        : "r"(A[0]), "r"(A[1]), "r"(A[2]), "r"(A[3]), "r"(B0), "r"(B1))

__global__ void __launch_bounds__(256, 1) k_gemm(
    const float* __restrict__ x, const float* __restrict__ K1,
    const float* __restrict__ K2, const float* __restrict__ W)
{
    extern __shared__ __nv_bfloat16 smem[];
    __nv_bfloat16* sK1h = smem;                    // [128][PADK]
    __nv_bfloat16* sK1l = sK1h + F_IN * PADK;
    __nv_bfloat16* sK2h = sK1l + F_IN * PADK;
    __nv_bfloat16* sK2l = sK2h + F_IN * PADK;
    __nv_bfloat16* sWh  = sK2l + F_IN * PADK;      // [64][PADK]
    __nv_bfloat16* sWl  = sWh + D_OUT * PADK;
    __nv_bfloat16* sXh  = sWl + D_OUT * PADK;      // [64][PADK]
    __nv_bfloat16* sXl  = sXh + 64 * PADK;
    float* sD1 = (float*)(sXl + 64 * PADK);        // [64][2]
    float* sD2 = sD1 + 128;                        // [64][2]

    int tid = threadIdx.x;

    // ---- load + transpose + split weights (once per block) ----
    for (int i = tid; i < F_IN * F_IN; i += 256) {
        int k = i >> 7, n = i & 127;
        __nv_bfloat16 h, l;
        bsplit(K1[i], h, l); sK1h[n * PADK + k] = h; sK1l[n * PADK + k] = l;
        bsplit(K2[i], h, l); sK2h[n * PADK + k] = h; sK2l[n * PADK + k] = l;
    }
    for (int i = tid; i < F_IN * D_OUT; i += 256) {
        int k = i >> 6, n = i & 63;
        __nv_bfloat16 h, l;
        bsplit(W[i], h, l); sWh[n * PADK + k] = h; sWl[n * PADK + k] = l;
    }

    int w = tid >> 5, lane = tid & 31;
    int g = lane >> 2, tig = lane & 3;
    int wr = w >> 1, wc = w & 1;
    int r0 = wr * 16;

    float4 mn = ((const float4*)g_mean)[lane];
    float4 rs = ((const float4*)g_rstd)[lane];

    const int ntiles = (N_NODES + 63) / 64;
    for (int tile = blockIdx.x; tile < ntiles; tile += gridDim.x) {
        int node0 = tile * 64;
        __syncthreads();   // prior tile fully consumed (sX, sD)

        // ---- load + BN + split x tile ----
        #pragma unroll
        for (int rr = 0; rr < 8; ++rr) {
            int r = w * 8 + rr;
            int gn = node0 + r;
            float4 xv = make_float4(0.f, 0.f, 0.f, 0.f);
            if (gn < N_NODES) xv = ((const float4*)x)[(size_t)gn * (F_IN / 4) + lane];
            float xn[4];
            xn[0] = (xv.x - mn.x) * rs.x;
            xn[1] = (xv.y - mn.y) * rs.y;
            xn[2] = (xv.z - mn.z) * rs.z;
            xn[3] = (xv.w - mn.w) * rs.w;
            __nv_bfloat16 h[4], l[4];
            #pragma unroll
            for (int c = 0; c < 4; ++c) bsplit(xn[c], h[c], l[c]);
            int base = r * PADK + 4 * lane;
            *(__nv_bfloat162*)&sXh[base]     = __nv_bfloat162(h[0], h[1]);
            *(__nv_bfloat162*)&sXh[base + 2] = __nv_bfloat162(h[2], h[3]);
            *(__nv_bfloat162*)&sXl[base]     = __nv_bfloat162(l[0], l[1]);
            *(__nv_bfloat162*)&sXl[base + 2] = __nv_bfloat162(l[2], l[3]);
        }
        __syncthreads();

        // ---- MMA: rows r0..r0+15, cols (wc half) of [K1|K2|W] ----
        float aK1[8][4], aK2[8][4], aW[4][4];
        #pragma unroll
        for (int t = 0; t < 8; ++t)
            #pragma unroll
            for (int i = 0; i < 4; ++i) { aK1[t][i] = 0.f; aK2[t][i] = 0.f; }
        #pragma unroll
        for (int t = 0; t < 4; ++t)
            #pragma unroll
            for (int i = 0; i < 4; ++i) aW[t][i] = 0.f;

        #pragma unroll
        for (int ks = 0; ks < 8; ++ks) {
            int k0 = ks * 16;
            uint32_t ah[4], al[4];
            int ra = (r0 + g) * PADK + k0 + 2 * tig;
            int rb = (r0 + g + 8) * PADK + k0 + 2 * tig;
            ah[0] = *(const uint32_t*)&sXh[ra];
            ah[1] = *(const uint32_t*)&sXh[rb];
            ah[2] = *(const uint32_t*)&sXh[ra + 8];
            ah[3] = *(const uint32_t*)&sXh[rb + 8];
            al[0] = *(const uint32_t*)&sXl[ra];
            al[1] = *(const uint32_t*)&sXl[rb];
            al[2] = *(const uint32_t*)&sXl[ra + 8];
            al[3] = *(const uint32_t*)&sXl[rb + 8];

            #pragma unroll
            for (int t = 0; t < 8; ++t) {
                int nb = (wc * 64 + t * 8 + g) * PADK + k0 + 2 * tig;
                uint32_t bh0 = *(const uint32_t*)&sK1h[nb];
                uint32_t bh1 = *(const uint32_t*)&sK1h[nb + 8];
                uint32_t bl0 = *(const uint32_t*)&sK1l[nb];
                uint32_t bl1 = *(const uint32_t*)&sK1l[nb + 8];
                MMA16816(aK1[t], ah, bh0, bh1);
                MMA16816(aK1[t], ah, bl0, bl1);
                MMA16816(aK1[t], al, bh0, bh1);
            }
            #pragma unroll
            for (int t = 0; t < 8; ++t) {
                int nb = (wc * 64 + t * 8 + g) * PADK + k0 + 2 * tig;
                uint32_t bh0 = *(const uint32_t*)&sK2h[nb];
                uint32_t bh1 = *(const uint32_t*)&sK2h[nb + 8];
                uint32_t bl0 = *(const uint32_t*)&sK2l[nb];
                uint32_t bl1 = *(const uint32_t*)&sK2l[nb + 8];
                MMA16816(aK2[t], ah, bh0, bh1);
                MMA16816(aK2[t], ah, bl0, bl1);
                MMA16816(aK2[t], al, bh0, bh1);
            }
            #pragma unroll
            for (int t = 0; t < 4; ++t) {
                int nb = (wc * 32 + t * 8 + g) * PADK + k0 + 2 * tig;
                uint32_t bh0 = *(const uint32_t*)&sWh[nb];
                uint32_t bh1 = *(const uint32_t*)&sWh[nb + 8];
                uint32_t bl0 = *(const uint32_t*)&sWl[nb];
                uint32_t bl1 = *(const uint32_t*)&sWl[nb + 8];
                MMA16816(aW[t], ah, bh0, bh1);
                MMA16816(aW[t], ah, bl0, bl1);
                MMA16816(aW[t], al, bh0, bh1);
            }
        }

        // ---- quadratic-form rowdots from fragments ----
        {
            int rA = r0 + g, rB = r0 + g + 8;
            float p0 = 0.f, p1 = 0.f, q0 = 0.f, q1 = 0.f;
            #pragma unroll
            for (int t = 0; t < 8; ++t) {
                int c0 = wc * 64 + t * 8 + 2 * tig;
                float xA0 = __bfloat162float(sXh[rA * PADK + c0])     + __bfloat162float(sXl[rA * PADK + c0]);
                float xA1 = __bfloat162float(sXh[rA * PADK + c0 + 1]) + __bfloat162float(sXl[rA * PADK + c0 + 1]);
                float xB0 = __bfloat162float(sXh[rB * PADK + c0])     + __bfloat162float(sXl[rB * PADK + c0]);
                float xB1 = __bfloat162float(sXh[rB * PADK + c0 + 1]) + __bfloat162float(sXl[rB * PADK + c0 + 1]);
                p0 += aK1[t][0] * xA0 + aK1[t][1] * xA1;
                p1 += aK1[t][2] * xB0 + aK1[t][3] * xB1;
                q0 += aK2[t][0] * xA0 + aK2[t][1] * xA1;
                q1 += aK2[t][2] * xB0 + aK2[t][3] * xB1;
            }
            p0 += __shfl_xor_sync(0xffffffffu, p0, 1); p0 += __shfl_xor_sync(0xffffffffu, p0, 2);
            p1 += __shfl_xor_sync(0xffffffffu, p1, 1); p1 += __shfl_xor_sync(0xffffffffu, p1, 2);
            q0 += __shfl_xor_sync(0xffffffffu, q0, 1); q0 += __shfl_xor_sync(0xffffffffu, q0, 2);
            q1 += __shfl_xor_sync(0xffffffffu, q1, 1); q1 += __shfl_xor_sync(0xffffffffu, q1, 2);
            if (tig == 0) {
                sD1[rA * 2 + wc] = p0; sD1[rB * 2 + wc] = p1;
                sD2[rA * 2 + wc] = q0; sD2[rB * 2 + wc] = q1;
            }
        }

        // ---- store mapped = xn @ W ----
        #pragma unroll
        for (int t = 0; t < 4; ++t) {
            int c0 = wc * 32 + t * 8 + 2 * tig;
            int gA = node0 + r0 + g, gB = gA + 8;
            if (gA < N_NODES)
                *(float2*)&g_mapped[(size_t)gA * D_OUT + c0] = make_float2(aW[t][0], aW[t][1]);
            if (gB < N_NODES)
                *(float2*)&g_mapped[(size_t)gB * D_OUT + c0] = make_float2(aW[t][2], aW[t][3]);
        }

        __syncthreads();
        if (tid < 64) {
            int gn = node0 + tid;
            if (gn < N_NODES) {
                g_a1[gn] = tanhf(sD1[tid * 2] + sD1[tid * 2 + 1]);
                g_a2[gn] = tanhf(sD2[tid * 2] + sD2[tid * 2 + 1]);
            }
        }
    }
}

// ---------------- fused single-pass softmax + SpMM + tanh -----------------------
// Shfl-batched: 32 lanes cooperatively load 32 (dst, weight) pairs in parallel,
// then broadcast them so the gather loop has all addresses known 32-ahead (high
// MLP, hides L2 latency). Softmax shift dropped: |e| <= 2*max|v|, exp safe.
__global__ void k_spmm(float* __restrict__ out) {
    int node = blockIdx.x * 8 + (threadIdx.x >> 5);
    if (node >= N_NODES) return;
    int lane = threadIdx.x & 31;
    int s = g_rowptr[node];
    int e = g_rowptr[node + 1];
    float a1i = g_a1[node];

    float2 acc = make_float2(0.f, 0.f);
    float den = 0.f;
    const float2* map2 = (const float2*)g_mapped;

    for (int base = s; base < e; base += 32) {
        int j = base + lane;
        int d = 0; float wgt = 0.f;
        if (j < e) {
            d = g_cdst[j];
            float v = g_cval[j];
            float t = v * (a1i + g_a2[d]);
            t = t > 0.f ? t : 0.2f * t;
            wgt = __expf(t);
        }
        int m = min(32, e - base);
        #pragma unroll 4
        for (int jj = 0; jj < m; ++jj) {
            float wj = __shfl_sync(0xffffffffu, wgt, jj);
            int   dj = __shfl_sync(0xffffffffu, d, jj);
            float2 md = map2[(size_t)dj * 32 + lane];
            den += wj;
            acc.x += wj * md.x;
            acc.y += wj * md.y;
        }
    }
    float2 o;
    if (e > s) {
        float inv = 1.f / den;
        o.x = tanhf(acc.x * inv);
        o.y = tanhf(acc.y * inv);
    } else {
        o = make_float2(0.f, 0.f);
    }
    ((float2*)out)[(size_t)node * 32 + lane] = o;
}

// ---------------- launch ---------------------------------------------------------
extern "C" void kernel_launch(void* const* d_in, const int* in_sizes, int n_in,
                              void* d_out, int out_size) {
    const float* x    = (const float*)d_in[0];
    const int*   src  = (const int*)d_in[1];
    const int*   dst  = (const int*)d_in[2];
    const float* vals = (const float*)d_in[3];
    const float* W    = (const float*)d_in[4];
    const float* K1   = (const float*)d_in[5];
    const float* K2   = (const float*)d_in[6];
    float* out = (float*)d_out;

    // lazily-created side stream + fork/join events (host objects only; no
    // device memory). Graph capture translates event record/wait into edges.
    static cudaStream_t s2 = nullptr;
    static cudaEvent_t evA = nullptr, evB = nullptr;
    if (!s2) {
        cudaStreamCreateWithFlags(&s2, cudaStreamNonBlocking);
        cudaEventCreateWithFlags(&evA, cudaEventDisableTiming);
        cudaEventCreateWithFlags(&evB, cudaEventDisableTiming);
    }

    const int NB = (N_NODES + 1023) / 1024;
    const int EB = (N_EDGES + 255) / 256;

    // common prologue (zeroes deg + stats accumulators)
    k_zero<<<512, 256>>>();

    // fork: CSR chain on s2, stats+gemm on main stream
    cudaEventRecord(evA, 0);
    cudaStreamWaitEvent(s2, evA, 0);

    k_colstats<<<1184, 256>>>(x);
    k_finalize_stats<<<1, 128>>>();

    k_hist<<<EB, 256, 0, s2>>>(src);
    k_scan1<<<NB, 1024, 0, s2>>>();
    k_scan2<<<1, 128, 0, s2>>>(NB);
    k_scan3<<<NB, 1024, 0, s2>>>();
    k_scatter<<<EB, 256, 0, s2>>>(src, dst, vals);
    cudaEventRecord(evB, s2);

    size_t smem = (size_t)(4 * F_IN * PADK + 2 * D_OUT * PADK + 2 * 64 * PADK) * sizeof(__nv_bfloat16)
                + 256 * sizeof(float);
    cudaFuncSetAttribute(k_gemm, cudaFuncAttributeMaxDynamicSharedMemorySize, (int)smem);
    k_gemm<<<148, 256, smem>>>(x, K1, K2, W);

    // join: spmm needs gemm (stream order) + CSR (event)
    cudaStreamWaitEvent(0, evB, 0);
    k_spmm<<<(N_NODES + 7) / 8, 256>>>(out);
}

// round 6
// speedup vs baseline: 2.0895x; 1.0246x over previous
#include <cuda_runtime.h>
#include <cuda_bf16.h>
#include <stdint.h>
#include <math.h>

#define N_NODES 100000
#define N_EDGES 1600000
#define F_IN 128
#define D_OUT 64
#define PADK 136   // bf16 elems per smem row (128 + 8 pad; 272B row stride, 16B-aligned)

static __device__ __constant__ float c_eps = 1e-3f;

// ---------------- scratch ------------------------------------------------------
__device__ float g_colsum[F_IN];
__device__ float g_colsq[F_IN];
__device__ float g_mean[F_IN];
__device__ float g_rstd[F_IN];
__device__ float g_a1[N_NODES];
__device__ float g_a2[N_NODES];
__device__ float g_mapped[(size_t)N_NODES * D_OUT];
__device__ int   g_deg[N_NODES];
__device__ int   g_cur[N_NODES];
__device__ int   g_rowptr[N_NODES + 1];
__device__ int   g_bsum[128];
__device__ int   g_bscan[128];
__device__ int2  g_cedge[N_EDGES];   // (dst, float bits) packed

// ---------------- small kernels -------------------------------------------------
__global__ void k_zero() {
    int i = blockIdx.x * blockDim.x + threadIdx.x;
    int stride = gridDim.x * blockDim.x;
    for (; i < N_NODES; i += stride) {
        g_deg[i] = 0;
        if (i < F_IN) { g_colsum[i] = 0.f; g_colsq[i] = 0.f; }
    }
}

__global__ void k_colstats(const float* __restrict__ x) {
    int f = threadIdx.x & 127;
    int half = threadIdx.x >> 7;
    float s = 0.f, sq = 0.f;
    for (int row = blockIdx.x * 2 + half; row < N_NODES; row += gridDim.x * 2) {
        float v = x[(size_t)row * F_IN + f];
        s += v; sq += v * v;
    }
    atomicAdd(&g_colsum[f], s);
    atomicAdd(&g_colsq[f], sq);
}

__global__ void k_finalize_stats() {
    int f = threadIdx.x;
    float mean = g_colsum[f] / (float)N_NODES;
    float var  = g_colsq[f] / (float)N_NODES - mean * mean;
    g_mean[f] = mean;
    g_rstd[f] = rsqrtf(var + c_eps);
}

__global__ void k_hist(const int* __restrict__ src) {
    int i = blockIdx.x * blockDim.x + threadIdx.x;
    if (i < N_EDGES) atomicAdd(&g_deg[src[i]], 1);
}

__global__ void k_scan1() {
    __shared__ int sh[1024];
    int tid = threadIdx.x;
    int i = blockIdx.x * 1024 + tid;
    int v = (i < N_NODES) ? g_deg[i] : 0;
    sh[tid] = v;
    __syncthreads();
    for (int off = 1; off < 1024; off <<= 1) {
        int t = (tid >= off) ? sh[tid - off] : 0;
        __syncthreads();
        sh[tid] += t;
        __syncthreads();
    }
    if (i < N_NODES) g_rowptr[i + 1] = sh[tid];
    if (tid == 1023) g_bsum[blockIdx.x] = sh[1023];
}

__global__ void k_scan2(int nb) {
    __shared__ int sh[128];
    int t = threadIdx.x;
    int v = (t < nb) ? g_bsum[t] : 0;
    sh[t] = v;
    __syncthreads();
    for (int off = 1; off < 128; off <<= 1) {
        int u = (t >= off) ? sh[t - off] : 0;
        __syncthreads();
        sh[t] += u;
        __syncthreads();
    }
    if (t < nb) g_bscan[t] = sh[t];
}

__global__ void k_scan3() {
    int tid = threadIdx.x;
    int i = blockIdx.x * 1024 + tid;
    int add = (blockIdx.x > 0) ? g_bscan[blockIdx.x - 1] : 0;
    if (i < N_NODES) {
        g_rowptr[i + 1] += add;
        g_cur[i] = 0;
    }
    if (i == 0) g_rowptr[0] = 0;
}

__global__ void k_scatter(const int* __restrict__ src, const int* __restrict__ dst,
                          const float* __restrict__ vals) {
    int i = blockIdx.x * blockDim.x + threadIdx.x;
    if (i < N_EDGES) {
        int s = src[i];
        int p = g_rowptr[s] + atomicAdd(&g_cur[s], 1);
        g_cedge[p] = make_int2(dst[i], __float_as_int(vals[i]));
    }
}

// ---------------- tensor-core GEMM block ----------------------------------------
// BN + xn@[K1|K2|W] via mma.sync m16n8k16 bf16, 3-term hi/lo split.
// Fragment loads via ldmatrix.x4 (1 LDSM per {bh0,bh1,bl0,bl1} quad).

__device__ __forceinline__ void bsplit(float v, __nv_bfloat16& h, __nv_bfloat16& l) {
    h = __float2bfloat16(v);
    l = __float2bfloat16(v - __bfloat162float(h));
}

#define MMA16816(D, A, B0, B1)                                               \
    asm volatile(                                                            \
        "mma.sync.aligned.m16n8k16.row.col.f32.bf16.bf16.f32 "              \
        "{%0,%1,%2,%3}, {%4,%5,%6,%7}, {%8,%9}, {%0,%1,%2,%3};"             \
        : "+f"(D[0]), "+f"(D[1]), "+f"(D[2]), "+f"(D[3])                     \
        : "r"(A[0]), "r"(A[1]), "r"(A[2]), "r"(A[3]), "r"(B0), "r"(B1))

#define LDSM4(R0, R1, R2, R3, ADDR)                                          \
    asm volatile("ldmatrix.sync.aligned.m8n8.x4.shared.b16 {%0,%1,%2,%3}, [%4];" \
        : "=r"(R0), "=r"(R1), "=r"(R2), "=r"(R3) : "r"(ADDR))

__global__ void __launch_bounds__(256, 1) k_gemm(
    const float* __restrict__ x, const float* __restrict__ K1,
    const float* __restrict__ K2, const float* __restrict__ W)
{
    extern __shared__ __nv_bfloat16 smem[];
    __nv_bfloat16* sK1h = smem;                    // [128][PADK]
    __nv_bfloat16* sK1l = sK1h + F_IN * PADK;
    __nv_bfloat16* sK2h = sK1l + F_IN * PADK;
    __nv_bfloat16* sK2l = sK2h + F_IN * PADK;
    __nv_bfloat16* sWh  = sK2l + F_IN * PADK;      // [64][PADK]
    __nv_bfloat16* sWl  = sWh + D_OUT * PADK;
    __nv_bfloat16* sXh  = sWl + D_OUT * PADK;      // [64][PADK]
    __nv_bfloat16* sXl  = sXh + 64 * PADK;
    float* sD1 = (float*)(sXl + 64 * PADK);        // [64][2]
    float* sD2 = sD1 + 128;                        // [64][2]

    int tid = threadIdx.x;

    // ---- load + transpose + split weights (once per block) ----
    for (int i = tid; i < F_IN * F_IN; i += 256) {
        int k = i >> 7, n = i & 127;
        __nv_bfloat16 h, l;
        bsplit(K1[i], h, l); sK1h[n * PADK + k] = h; sK1l[n * PADK + k] = l;
        bsplit(K2[i], h, l); sK2h[n * PADK + k] = h; sK2l[n * PADK + k] = l;
    }
    for (int i = tid; i < F_IN * D_OUT; i += 256) {
        int k = i >> 6, n = i & 63;
        __nv_bfloat16 h, l;
        bsplit(W[i], h, l); sWh[n * PADK + k] = h; sWl[n * PADK + k] = l;
    }

    int w = tid >> 5, lane = tid & 31;
    int g = lane >> 2, tig = lane & 3;
    int wr = w >> 1, wc = w & 1;
    int r0 = wr * 16;

    // shared-state-space base addresses (bytes) for ldmatrix
    uint32_t sXh_s = (uint32_t)__cvta_generic_to_shared(sXh);
    uint32_t sXl_s = (uint32_t)__cvta_generic_to_shared(sXl);
    uint32_t sK1h_s = (uint32_t)__cvta_generic_to_shared(sK1h);
    uint32_t sK1l_s = (uint32_t)__cvta_generic_to_shared(sK1l);
    uint32_t sK2h_s = (uint32_t)__cvta_generic_to_shared(sK2h);
    uint32_t sK2l_s = (uint32_t)__cvta_generic_to_shared(sK2l);
    uint32_t sWh_s  = (uint32_t)__cvta_generic_to_shared(sWh);
    uint32_t sWl_s  = (uint32_t)__cvta_generic_to_shared(sWl);

    // per-lane ldmatrix addressing
    // A (x4 = {rows0-7@k0, rows8-15@k0, rows0-7@k0+8, rows8-15@k0+8}):
    int aRow = r0 + (lane & 7) + ((lane >> 3) & 1) * 8;
    int aKof = (lane >> 4) * 8;
    uint32_t aByte = (uint32_t)(aRow * PADK + aKof) * 2;   // + k0*2 per step
    // B (x4 = {hi@k0, hi@k0+8, lo@k0, lo@k0+8}); row = n0 + (lane&7):
    int bRow = lane & 7;
    int bKof = ((lane >> 3) & 1) * 8;
    int bLo  = (lane >> 4) & 1;                             // 0 = hi array, 1 = lo array
    uint32_t bByte = (uint32_t)(bRow * PADK + bKof) * 2;    // + (n0*PADK + k0)*2 per use

    float4 mn = ((const float4*)g_mean)[lane];
    float4 rs = ((const float4*)g_rstd)[lane];

    const int ntiles = (N_NODES + 63) / 64;
    for (int tile = blockIdx.x; tile < ntiles; tile += gridDim.x) {
        int node0 = tile * 64;
        __syncthreads();   // prior tile fully consumed

        // ---- load + BN + split x tile ----
        #pragma unroll
        for (int rr = 0; rr < 8; ++rr) {
            int r = w * 8 + rr;
            int gn = node0 + r;
            float4 xv = make_float4(0.f, 0.f, 0.f, 0.f);
            if (gn < N_NODES) xv = ((const float4*)x)[(size_t)gn * (F_IN / 4) + lane];
            float xn[4];
            xn[0] = (xv.x - mn.x) * rs.x;
            xn[1] = (xv.y - mn.y) * rs.y;
            xn[2] = (xv.z - mn.z) * rs.z;
            xn[3] = (xv.w - mn.w) * rs.w;
            __nv_bfloat16 h[4], l[4];
            #pragma unroll
            for (int c = 0; c < 4; ++c) bsplit(xn[c], h[c], l[c]);
            int base = r * PADK + 4 * lane;
            *(__nv_bfloat162*)&sXh[base]     = __nv_bfloat162(h[0], h[1]);
            *(__nv_bfloat162*)&sXh[base + 2] = __nv_bfloat162(h[2], h[3]);
            *(__nv_bfloat162*)&sXl[base]     = __nv_bfloat162(l[0], l[1]);
            *(__nv_bfloat162*)&sXl[base + 2] = __nv_bfloat162(l[2], l[3]);
        }
        __syncthreads();

        float aK1[8][4], aK2[8][4], aW[4][4];
        #pragma unroll
        for (int t = 0; t < 8; ++t)
            #pragma unroll
            for (int i = 0; i < 4; ++i) { aK1[t][i] = 0.f; aK2[t][i] = 0.f; }
        #pragma unroll
        for (int t = 0; t < 4; ++t)
            #pragma unroll
            for (int i = 0; i < 4; ++i) aW[t][i] = 0.f;

        #pragma unroll
        for (int ks = 0; ks < 8; ++ks) {
            uint32_t k0b = (uint32_t)(ks * 16) * 2;   // k0 in bytes
            uint32_t ah[4], al[4];
            LDSM4(ah[0], ah[1], ah[2], ah[3], sXh_s + aByte + k0b);
            LDSM4(al[0], al[1], al[2], al[3], sXl_s + aByte + k0b);

            #pragma unroll
            for (int t = 0; t < 8; ++t) {
                int n0 = wc * 64 + t * 8;
                uint32_t addr = (bLo ? sK1l_s : sK1h_s) + bByte + (uint32_t)(n0 * PADK) * 2 + k0b;
                uint32_t bh0, bh1, bl0, bl1;
                LDSM4(bh0, bh1, bl0, bl1, addr);
                MMA16816(aK1[t], ah, bh0, bh1);
                MMA16816(aK1[t], ah, bl0, bl1);
                MMA16816(aK1[t], al, bh0, bh1);
            }
            #pragma unroll
            for (int t = 0; t < 8; ++t) {
                int n0 = wc * 64 + t * 8;
                uint32_t addr = (bLo ? sK2l_s : sK2h_s) + bByte + (uint32_t)(n0 * PADK) * 2 + k0b;
                uint32_t bh0, bh1, bl0, bl1;
                LDSM4(bh0, bh1, bl0, bl1, addr);
                MMA16816(aK2[t], ah, bh0, bh1);
                MMA16816(aK2[t], ah, bl0, bl1);
                MMA16816(aK2[t], al, bh0, bh1);
            }
            #pragma unroll
            for (int t = 0; t < 4; ++t) {
                int n0 = wc * 32 + t * 8;
                uint32_t addr = (bLo ? sWl_s : sWh_s) + bByte + (uint32_t)(n0 * PADK) * 2 + k0b;
                uint32_t bh0, bh1, bl0, bl1;
                LDSM4(bh0, bh1, bl0, bl1, addr);
                MMA16816(aW[t], ah, bh0, bh1);
                MMA16816(aW[t], ah, bl0, bl1);
                MMA16816(aW[t], al, bh0, bh1);
            }
        }

        // ---- quadratic-form rowdots from fragments (vectorized xn loads) ----
        {
            int rA = r0 + g, rB = r0 + g + 8;
            float p0 = 0.f, p1 = 0.f, q0 = 0.f, q1 = 0.f;
            #pragma unroll
            for (int t = 0; t < 8; ++t) {
                int c0 = wc * 64 + t * 8 + 2 * tig;
                float2 hA = __bfloat1622float2(*(const __nv_bfloat162*)&sXh[rA * PADK + c0]);
                float2 lA = __bfloat1622float2(*(const __nv_bfloat162*)&sXl[rA * PADK + c0]);
                float2 hB = __bfloat1622float2(*(const __nv_bfloat162*)&sXh[rB * PADK + c0]);
                float2 lB = __bfloat1622float2(*(const __nv_bfloat162*)&sXl[rB * PADK + c0]);
                float xA0 = hA.x + lA.x, xA1 = hA.y + lA.y;
                float xB0 = hB.x + lB.x, xB1 = hB.y + lB.y;
                p0 += aK1[t][0] * xA0 + aK1[t][1] * xA1;
                p1 += aK1[t][2] * xB0 + aK1[t][3] * xB1;
                q0 += aK2[t][0] * xA0 + aK2[t][1] * xA1;
                q1 += aK2[t][2] * xB0 + aK2[t][3] * xB1;
            }
            p0 += __shfl_xor_sync(0xffffffffu, p0, 1); p0 += __shfl_xor_sync(0xffffffffu, p0, 2);
            p1 += __shfl_xor_sync(0xffffffffu, p1, 1); p1 += __shfl_xor_sync(0xffffffffu, p1, 2);
            q0 += __shfl_xor_sync(0xffffffffu, q0, 1); q0 += __shfl_xor_sync(0xffffffffu, q0, 2);
            q1 += __shfl_xor_sync(0xffffffffu, q1, 1); q1 += __shfl_xor_sync(0xffffffffu, q1, 2);
            if (tig == 0) {
                sD1[rA * 2 + wc] = p0; sD1[rB * 2 + wc] = p1;
                sD2[rA * 2 + wc] = q0; sD2[rB * 2 + wc] = q1;
            }
        }

        // ---- store mapped = xn @ W ----
        #pragma unroll
        for (int t = 0; t < 4; ++t) {
            int c0 = wc * 32 + t * 8 + 2 * tig;
            int gA = node0 + r0 + g, gB = gA + 8;
            if (gA < N_NODES)
                *(float2*)&g_mapped[(size_t)gA * D_OUT + c0] = make_float2(aW[t][0], aW[t][1]);
            if (gB < N_NODES)
                *(float2*)&g_mapped[(size_t)gB * D_OUT + c0] = make_float2(aW[t][2], aW[t][3]);
        }

        __syncthreads();
        if (tid < 64) {
            int gn = node0 + tid;
            if (gn < N_NODES) {
                g_a1[gn] = tanhf(sD1[tid * 2] + sD1[tid * 2 + 1]);
                g_a2[gn] = tanhf(sD2[tid * 2] + sD2[tid * 2 + 1]);
            }
        }
    }
}

// ---------------- fused single-pass softmax + SpMM + tanh -----------------------
__global__ void k_spmm(float* __restrict__ out) {
    int node = blockIdx.x * 8 + (threadIdx.x >> 5);
    if (node >= N_NODES) return;
    int lane = threadIdx.x & 31;
    int s = g_rowptr[node];
    int e = g_rowptr[node + 1];
    float a1i = g_a1[node];

    float2 acc = make_float2(0.f, 0.f);
    float den = 0.f;
    const float2* map2 = (const float2*)g_mapped;

    for (int base = s; base < e; base += 32) {
        int j = base + lane;
        int d = 0; float wgt = 0.f;
        if (j < e) {
            int2 ed = g_cedge[j];
            d = ed.x;
            float v = __int_as_float(ed.y);
            float t = v * (a1i + g_a2[d]);
            t = t > 0.f ? t : 0.2f * t;
            wgt = __expf(t);
        }
        int m = min(32, e - base);
        #pragma unroll 4
        for (int jj = 0; jj < m; ++jj) {
            float wj = __shfl_sync(0xffffffffu, wgt, jj);
            int   dj = __shfl_sync(0xffffffffu, d, jj);
            float2 md = map2[(size_t)dj * 32 + lane];
            den += wj;
            acc.x += wj * md.x;
            acc.y += wj * md.y;
        }
    }
    float2 o;
    if (e > s) {
        float inv = 1.f / den;
        o.x = tanhf(acc.x * inv);
        o.y = tanhf(acc.y * inv);
    } else {
        o = make_float2(0.f, 0.f);
    }
    ((float2*)out)[(size_t)node * 32 + lane] = o;
}

// ---------------- launch ---------------------------------------------------------
extern "C" void kernel_launch(void* const* d_in, const int* in_sizes, int n_in,
                              void* d_out, int out_size) {
    const float* x    = (const float*)d_in[0];
    const int*   src  = (const int*)d_in[1];
    const int*   dst  = (const int*)d_in[2];
    const float* vals = (const float*)d_in[3];
    const float* W    = (const float*)d_in[4];
    const float* K1   = (const float*)d_in[5];
    const float* K2   = (const float*)d_in[6];
    float* out = (float*)d_out;

    static cudaStream_t s2 = nullptr;
    static cudaEvent_t evA = nullptr, evB = nullptr;
    if (!s2) {
        cudaStreamCreateWithFlags(&s2, cudaStreamNonBlocking);
        cudaEventCreateWithFlags(&evA, cudaEventDisableTiming);
        cudaEventCreateWithFlags(&evB, cudaEventDisableTiming);
    }

    const int NB = (N_NODES + 1023) / 1024;
    const int EB = (N_EDGES + 255) / 256;

    k_zero<<<512, 256>>>();

    cudaEventRecord(evA, 0);
    cudaStreamWaitEvent(s2, evA, 0);

    k_colstats<<<1184, 256>>>(x);
    k_finalize_stats<<<1, 128>>>();

    k_hist<<<EB, 256, 0, s2>>>(src);
    k_scan1<<<NB, 1024, 0, s2>>>();
    k_scan2<<<1, 128, 0, s2>>>(NB);
    k_scan3<<<NB, 1024, 0, s2>>>();
    k_scatter<<<EB, 256, 0, s2>>>(src, dst, vals);
    cudaEventRecord(evB, s2);

    size_t smem = (size_t)(4 * F_IN * PADK + 2 * D_OUT * PADK + 2 * 64 * PADK) * sizeof(__nv_bfloat16)
                + 256 * sizeof(float);
    cudaFuncSetAttribute(k_gemm, cudaFuncAttributeMaxDynamicSharedMemorySize, (int)smem);
    k_gemm<<<148, 256, smem>>>(x, K1, K2, W);

    cudaStreamWaitEvent(0, evB, 0);
    k_spmm<<<(N_NODES + 7) / 8, 256>>>(out);
}